// round 1
// baseline (speedup 1.0000x reference)
#include <cuda_runtime.h>
#include <cuda_bf16.h>
#include <stdint.h>

// Problem sizes (fixed by the reference).
#define MM 8192
#define KK 4096
#define NN 4096

// Scratch (allocation-free: __device__ globals).
__device__ __align__(16) int8_t g_xq[(size_t)MM * KK];      // quantized activations, row-major [M][K]
__device__ __align__(16) int8_t g_wq[(size_t)NN * KK];      // weight int8, TRANSPOSED [N][K] (k contiguous)

// ---------------------------------------------------------------------------
// Kernel 1: static per-tensor symmetric quantization, fp32 -> int8.
// Matches jnp.round (round-half-to-even) via __float2int_rn, then clip.
// ---------------------------------------------------------------------------
__global__ void quantize_x_kernel(const float* __restrict__ x,
                                  const float* __restrict__ scale_ptr,
                                  int8_t* __restrict__ out, int n4) {
    int i = blockIdx.x * blockDim.x + threadIdx.x;
    if (i >= n4) return;
    float s = __ldg(scale_ptr);
    float4 v = reinterpret_cast<const float4*>(x)[i];
    int a = __float2int_rn(v.x / s);
    int b = __float2int_rn(v.y / s);
    int c = __float2int_rn(v.z / s);
    int d = __float2int_rn(v.w / s);
    a = min(127, max(-128, a));
    b = min(127, max(-128, b));
    c = min(127, max(-128, c));
    d = min(127, max(-128, d));
    char4 q;
    q.x = (char)a; q.y = (char)b; q.z = (char)c; q.w = (char)d;
    reinterpret_cast<char4*>(out)[i] = q;
}

// ---------------------------------------------------------------------------
// Kernel 2: repack weight int32 [K][N] -> int8 transposed [N][K].
// Tile: 128 (k) x 32 (n). Reads coalesced (consecutive n, 4B each),
// writes coalesced (char4 along k). smem padded to kill bank conflicts.
// ---------------------------------------------------------------------------
__global__ void repack_w_kernel(const int* __restrict__ w, int8_t* __restrict__ wq) {
    __shared__ char s[32][128 + 4];   // [n][k], row stride 132 (multiple of 4)
    int n0 = blockIdx.x * 32;
    int k0 = blockIdx.y * 128;
    int tid = threadIdx.x;            // 256 threads

    // Read phase: tid -> (n = tid&31, kb = tid>>5), 16 iterations over k.
    int n = tid & 31;
    int kb = tid >> 5;
#pragma unroll
    for (int i = 0; i < 16; i++) {
        int k = kb + i * 8;
        s[n][k] = (char)w[(size_t)(k0 + k) * NN + (n0 + n)];
    }
    __syncthreads();

    // Write phase: tid -> (kq = tid&31 handles 4 bytes of k, nn = tid>>5).
    int kq = tid & 31;
    int nn = tid >> 5;
#pragma unroll
    for (int i = 0; i < 4; i++) {
        int n2 = nn + i * 8;
        char4 v = *reinterpret_cast<const char4*>(&s[n2][kq * 4]);
        *reinterpret_cast<char4*>(&g_wq[(size_t)(n0 + n2) * KK + k0 + kq * 4]) = v;
        (void)wq;
    }
}

// ---------------------------------------------------------------------------
// Kernel 3: int8 GEMM via dp4a.
// C[m][n] = sum_k A[m][k]*B[n][k]; A = g_xq [M][K], B = g_wq [N][K].
// Block tile 128x128, BK=64. 256 threads (16x16), 8x8 acc per thread.
// smem layout: s[k_chunk][m] of packed-4k int32 => fragment loads are
// contiguous 8-int runs (2x LDS.128).
// ---------------------------------------------------------------------------
#define BM 128
#define BN 128
#define BK 64
#define KC (BK / 4)   // 16 packed k-chunks per tile

__global__ void __launch_bounds__(256, 2)
gemm_dp4a_kernel(const int8_t* __restrict__ A, const int8_t* __restrict__ B,
                 const float* __restrict__ bias,
                 const float* __restrict__ sa, const float* __restrict__ sb,
                 float* __restrict__ C) {
    __shared__ int a_s[KC][BM + 4];
    __shared__ int b_s[KC][BN + 4];

    int tid = threadIdx.x;
    int m_blk = blockIdx.y * BM;
    int n_blk = blockIdx.x * BN;

    int ty = tid >> 4;          // 0..15
    int tx = tid & 15;          // 0..15
    int m0 = ty * 8;
    int n0 = tx * 8;

    int acc[8][8];
#pragma unroll
    for (int i = 0; i < 8; i++)
#pragma unroll
        for (int j = 0; j < 8; j++) acc[i][j] = 0;

    // Global-load mapping: (k-chunk, row) = (tid&15, tid>>4 + 16*i)
    int lkk = tid & 15;
    int lm  = tid >> 4;
    const int* Ag = reinterpret_cast<const int*>(A + (size_t)m_blk * KK);
    const int* Bg = reinterpret_cast<const int*>(B + (size_t)n_blk * KK);
    const int krow = KK / 4;    // ints per row

    for (int kt = 0; kt < KK / BK; kt++) {
        int kbase = kt * KC;
#pragma unroll
        for (int i = 0; i < 8; i++) {
            int m = lm + i * 16;
            a_s[lkk][m] = Ag[(size_t)m * krow + kbase + lkk];
            b_s[lkk][m] = Bg[(size_t)m * krow + kbase + lkk];
        }
        __syncthreads();

#pragma unroll
        for (int kk = 0; kk < KC; kk++) {
            int af[8], bf[8];
#pragma unroll
            for (int i = 0; i < 8; i++) af[i] = a_s[kk][m0 + i];
#pragma unroll
            for (int j = 0; j < 8; j++) bf[j] = b_s[kk][n0 + j];
#pragma unroll
            for (int i = 0; i < 8; i++)
#pragma unroll
                for (int j = 0; j < 8; j++)
                    acc[i][j] = __dp4a(af[i], bf[j], acc[i][j]);
        }
        __syncthreads();
    }

    float scale = __ldg(sa) * __ldg(sb);
#pragma unroll
    for (int i = 0; i < 8; i++) {
        size_t m = (size_t)(m_blk + m0 + i);
        float4* crow = reinterpret_cast<float4*>(C + m * NN + n_blk + n0);
        const float4* brow = reinterpret_cast<const float4*>(bias + n_blk + n0);
#pragma unroll
        for (int j4 = 0; j4 < 2; j4++) {
            float4 bv = __ldg(&brow[j4]);
            float4 o;
            o.x = (float)acc[i][j4 * 4 + 0] * scale + bv.x;
            o.y = (float)acc[i][j4 * 4 + 1] * scale + bv.y;
            o.z = (float)acc[i][j4 * 4 + 2] * scale + bv.z;
            o.w = (float)acc[i][j4 * 4 + 3] * scale + bv.w;
            crow[j4] = o;
        }
    }
}

// ---------------------------------------------------------------------------
// Launch
// ---------------------------------------------------------------------------
extern "C" void kernel_launch(void* const* d_in, const int* in_sizes, int n_in,
                              void* d_out, int out_size) {
    const float* x       = (const float*)d_in[0];   // [M, K] fp32
    const int*   weight  = (const int*)  d_in[1];   // [K, N] int32 (int8 range)
    const float* bias    = (const float*)d_in[2];   // [N] fp32
    const float* in_sc   = (const float*)d_in[3];   // [1]
    const float* w_sc    = (const float*)d_in[4];   // [1]
    float*       out     = (float*)d_out;           // [M, N] fp32

    int8_t* xq; cudaGetSymbolAddress((void**)&xq, g_xq);
    int8_t* wq; cudaGetSymbolAddress((void**)&wq, g_wq);

    // 1) quantize activations
    {
        int n4 = (MM * KK) / 4;
        int threads = 256;
        int blocks = (n4 + threads - 1) / threads;
        quantize_x_kernel<<<blocks, threads>>>(x, in_sc, xq, n4);
    }
    // 2) repack + transpose weight
    {
        dim3 grid(NN / 32, KK / 128);
        repack_w_kernel<<<grid, 256>>>(weight, wq);
    }
    // 3) GEMM + dequant + bias
    {
        dim3 grid(NN / BN, MM / BM);
        gemm_dp4a_kernel<<<grid, 256>>>(xq, wq, bias, in_sc, w_sc, out);
    }
}

// round 5
// speedup vs baseline: 1.0835x; 1.0835x over previous
#include <cuda_runtime.h>
#include <cuda.h>
#include <cuda_bf16.h>
#include <stdint.h>

// Problem sizes (fixed).
#define MM 8192
#define KK 4096
#define NN 4096

// GEMM tiling.
#define BM 128
#define BN 128
#define BKB 128                  // K bytes per stage (one SW128 row)
#define STAGES 5
#define KITERS (KK / BKB)        // 32
#define KCH 4                    // k32 chunks per stage (128/32)

// SMEM layout (dynamic):
//   [0..40)  full[5] mbarriers
//   [1024 + s*32768)          A stage tile: 128 rows x 128B (16KB, SW128)
//   [1024 + s*32768 + 16384)  B stage tile: 128 rows x 128B (16KB, SW128)
#define SMEM_FULL(s)  ((s) * 8)
#define SMEM_A_OFF(s) (1024 + (s) * 32768)
#define SMEM_B_OFF(s) (1024 + (s) * 32768 + 16384)
#define SMEM_TOTAL    (1024 + STAGES * 32768)

// Scratch (allocation-free: __device__ globals).
__device__ __align__(1024) int8_t g_xq[(size_t)MM * KK];   // A int8 [M][K]
__device__ __align__(1024) int8_t g_wq[(size_t)NN * KK];   // B int8 [N][K] (k contiguous)

// ---------------------------------------------------------------------------
// PTX helpers (plain sm_103-safe: NO tcgen05 anywhere)
// ---------------------------------------------------------------------------
__device__ __forceinline__ uint32_t smem_u32(const void* p) {
    uint32_t a;
    asm("{ .reg .u64 t; cvta.to.shared.u64 t, %1; cvt.u32.u64 %0, t; }" : "=r"(a) : "l"(p));
    return a;
}

#define MBAR_INIT(a, cnt) \
    asm volatile("mbarrier.init.shared.b64 [%0], %1;" :: "r"(a), "r"(cnt) : "memory")
#define MBAR_EXPECT_TX(a, bytes) \
    asm volatile("mbarrier.arrive.expect_tx.shared.b64 _, [%0], %1;" :: "r"(a), "r"(bytes) : "memory")

#define MBAR_WAIT(a, ph) do {                                                   \
    uint32_t _m = (a), _p = (ph), _d;                                           \
    asm volatile("{ .reg .pred p; mbarrier.try_wait.parity.acquire.cta.shared::cta.b64 p, [%1], %2; selp.b32 %0, 1, 0, p; }" \
        : "=r"(_d) : "r"(_m), "r"(_p) : "memory");                              \
    if (!_d) {                                                                  \
        asm volatile("{ .reg .pred P; L1_%=: mbarrier.try_wait.parity.acquire.cta.shared::cta.b64 P, [%0], %1, 0x989680; @P bra.uni L2_%=; bra.uni L1_%=; L2_%=: }" \
            :: "r"(_m), "r"(_p) : "memory");                                    \
    }                                                                           \
} while (0)

#define TMA_LOAD_2D(dst, map, cx, cy, bar) \
    asm volatile("cp.async.bulk.tensor.2d.shared::cta.global.tile.mbarrier::complete_tx::bytes [%0], [%1, {%2, %3}], [%4];" \
        :: "r"(dst), "l"(map), "r"(cx), "r"(cy), "r"(bar) : "memory")

#define LDSM_X4(r0, r1, r2, r3, addr) \
    asm volatile("ldmatrix.sync.aligned.m8n8.x4.shared.b16 {%0,%1,%2,%3}, [%4];" \
        : "=r"(r0), "=r"(r1), "=r"(r2), "=r"(r3) : "r"(addr))

#define MMA_S8(d, a, b) \
    asm volatile("mma.sync.aligned.m16n8k32.row.col.s32.s8.s8.s32 " \
        "{%0,%1,%2,%3}, {%4,%5,%6,%7}, {%8,%9}, {%0,%1,%2,%3};" \
        : "+r"((d)[0]), "+r"((d)[1]), "+r"((d)[2]), "+r"((d)[3]) \
        : "r"((a)[0]), "r"((a)[1]), "r"((a)[2]), "r"((a)[3]), "r"((b)[0]), "r"((b)[1]))

// ---------------------------------------------------------------------------
// Kernel 1: quantize x fp32 -> int8 (round-half-even + clip), MLP=4.
// ---------------------------------------------------------------------------
__global__ void quantize_x_kernel(const float* __restrict__ x,
                                  const float* __restrict__ scale_ptr,
                                  int8_t* __restrict__ out) {
    int base = blockIdx.x * blockDim.x + threadIdx.x;
    int stride = gridDim.x * blockDim.x;
    float s = __ldg(scale_ptr);
    const float4* x4 = reinterpret_cast<const float4*>(x);
    char4* o4 = reinterpret_cast<char4*>(out);
    float4 v[4];
#pragma unroll
    for (int u = 0; u < 4; u++) v[u] = x4[base + u * stride];
#pragma unroll
    for (int u = 0; u < 4; u++) {
        int i = base + u * stride;
        int a = __float2int_rn(v[u].x / s);
        int b = __float2int_rn(v[u].y / s);
        int c = __float2int_rn(v[u].z / s);
        int d = __float2int_rn(v[u].w / s);
        a = min(127, max(-128, a)); b = min(127, max(-128, b));
        c = min(127, max(-128, c)); d = min(127, max(-128, d));
        char4 q; q.x = (char)a; q.y = (char)b; q.z = (char)c; q.w = (char)d;
        o4[i] = q;
    }
}

// ---------------------------------------------------------------------------
// Kernel 2: repack weight int32 [K][N] -> int8 [N][K].
// ---------------------------------------------------------------------------
__global__ void repack_w_kernel(const int* __restrict__ w) {
    __shared__ char s[32][128 + 4];
    int n0 = blockIdx.x * 32;
    int k0 = blockIdx.y * 128;
    int tid = threadIdx.x;
    int n = tid & 31, kb = tid >> 5;
#pragma unroll
    for (int i = 0; i < 16; i++) {
        int k = kb + i * 8;
        s[n][k] = (char)w[(size_t)(k0 + k) * NN + (n0 + n)];
    }
    __syncthreads();
    int kq = tid & 31, nn = tid >> 5;
#pragma unroll
    for (int i = 0; i < 4; i++) {
        int n2 = nn + i * 8;
        char4 v = *reinterpret_cast<const char4*>(&s[n2][kq * 4]);
        *reinterpret_cast<char4*>(&g_wq[(size_t)(n0 + n2) * KK + k0 + kq * 4]) = v;
    }
}

// ---------------------------------------------------------------------------
// Kernel 3: int8 GEMM: TMA-fed 5-stage pipeline + ldmatrix + mma.sync.s8.
// CTA 128x128, 256 threads = 8 warps (4M x 2N), warp tile 32x64.
// ---------------------------------------------------------------------------
__global__ void __launch_bounds__(256, 1)
gemm_i8_mma_kernel(const __grid_constant__ CUtensorMap tma_a,
                   const __grid_constant__ CUtensorMap tma_b,
                   const float* __restrict__ bias,
                   const float* __restrict__ sa, const float* __restrict__ sbp,
                   float* __restrict__ C) {
    extern __shared__ char smem[];
    uint32_t sb = smem_u32(smem);
    int tid = threadIdx.x;
    int wid = tid >> 5;
    int lane = tid & 31;
    int wm = wid & 3;            // 0..3 -> M offset wm*32
    int wn = wid >> 2;           // 0..1 -> N offset wn*64
    int m_blk = blockIdx.y * BM;
    int n_blk = blockIdx.x * BN;

    if (tid == 0) {
#pragma unroll
        for (int s = 0; s < STAGES; s++) MBAR_INIT(sb + SMEM_FULL(s), 1);
    }
    __syncthreads();

    // Prologue: fill STAGES-1 stages.
    if (tid == 0) {
#pragma unroll
        for (int s = 0; s < STAGES - 1; s++) {
            MBAR_EXPECT_TX(sb + SMEM_FULL(s), 32768u);
            TMA_LOAD_2D(sb + SMEM_A_OFF(s), &tma_a, s * BKB, m_blk, sb + SMEM_FULL(s));
            TMA_LOAD_2D(sb + SMEM_B_OFF(s), &tma_b, s * BKB, n_blk, sb + SMEM_FULL(s));
        }
    }

    // Per-lane ldmatrix addressing (SW128: phys_chunk = chunk ^ (row & 7)).
    int r7 = lane & 7;
    int a_row = wm * 32 + ((lane >> 3) & 1) * 8 + r7;   // + f*16
    int a_hi  = (lane >> 4) & 1;                        // chunk +1 for lanes 16-31
    int b_row = wn * 64 + ((lane >> 4) & 1) * 8 + r7;   // + g*16
    int b_hi  = (lane >> 3) & 1;

    int acc[2][8][4];
#pragma unroll
    for (int f = 0; f < 2; f++)
#pragma unroll
        for (int j = 0; j < 8; j++)
#pragma unroll
            for (int e = 0; e < 4; e++) acc[f][j][e] = 0;

    int s = 0, ph = 0;
    for (int it = 0; it < KITERS; it++) {
        MBAR_WAIT(sb + SMEM_FULL(s), (uint32_t)ph);

        uint32_t aS = sb + SMEM_A_OFF(s);
        uint32_t bS = sb + SMEM_B_OFF(s);
        uint32_t aBase0 = aS + (uint32_t)a_row * 128;
        uint32_t aBase1 = aBase0 + 16 * 128;
        uint32_t bBase0 = bS + (uint32_t)b_row * 128;

#pragma unroll
        for (int kc = 0; kc < KCH; kc++) {
            int ca = 2 * kc + a_hi;
            int cb = 2 * kc + b_hi;
            uint32_t aoff = (uint32_t)((ca ^ r7) << 4);
            uint32_t boff = (uint32_t)((cb ^ r7) << 4);

            uint32_t a0[4], a1[4];
            LDSM_X4(a0[0], a0[1], a0[2], a0[3], aBase0 + aoff);
            LDSM_X4(a1[0], a1[1], a1[2], a1[3], aBase1 + aoff);

            uint32_t bfr[8][2];
#pragma unroll
            for (int g = 0; g < 4; g++) {
                uint32_t t0, t1, t2, t3;
                LDSM_X4(t0, t1, t2, t3, bBase0 + (uint32_t)(g * 16 * 128) + boff);
                bfr[2 * g][0] = t0; bfr[2 * g][1] = t1;
                bfr[2 * g + 1][0] = t2; bfr[2 * g + 1][1] = t3;
            }

#pragma unroll
            for (int j = 0; j < 8; j++) {
                MMA_S8(acc[0][j], a0, bfr[j]);
                MMA_S8(acc[1][j], a1, bfr[j]);
            }
        }

        __syncthreads();   // all warps done with stage s before refill

        if (tid == 0 && it + STAGES - 1 < KITERS) {
            int nk = it + STAGES - 1;
            int ns = nk % STAGES;
            MBAR_EXPECT_TX(sb + SMEM_FULL(ns), 32768u);
            TMA_LOAD_2D(sb + SMEM_A_OFF(ns), &tma_a, nk * BKB, m_blk, sb + SMEM_FULL(ns));
            TMA_LOAD_2D(sb + SMEM_B_OFF(ns), &tma_b, nk * BKB, n_blk, sb + SMEM_FULL(ns));
        }

        if (++s == STAGES) { s = 0; ph ^= 1; }
    }

    // Epilogue: dequant + bias, float2 stores.
    float scale = __ldg(sa) * __ldg(sbp);
    int r = lane >> 2;
    int c2 = (lane & 3) * 2;
#pragma unroll
    for (int f = 0; f < 2; f++) {
        int row0 = m_blk + wm * 32 + f * 16 + r;
#pragma unroll
        for (int j = 0; j < 8; j++) {
            int col = n_blk + wn * 64 + j * 8 + c2;
            float2 bv = *reinterpret_cast<const float2*>(bias + col);
            float2 o0, o1;
            o0.x = (float)acc[f][j][0] * scale + bv.x;
            o0.y = (float)acc[f][j][1] * scale + bv.y;
            o1.x = (float)acc[f][j][2] * scale + bv.x;
            o1.y = (float)acc[f][j][3] * scale + bv.y;
            *reinterpret_cast<float2*>(C + (size_t)row0 * NN + col) = o0;
            *reinterpret_cast<float2*>(C + (size_t)(row0 + 8) * NN + col) = o1;
        }
    }
}

// ---------------------------------------------------------------------------
// Host launch
// ---------------------------------------------------------------------------
typedef CUresult (*EncodeTiledFn)(
    CUtensorMap*, CUtensorMapDataType, cuuint32_t, void*,
    const cuuint64_t*, const cuuint64_t*, const cuuint32_t*, const cuuint32_t*,
    CUtensorMapInterleave, CUtensorMapSwizzle, CUtensorMapL2promotion,
    CUtensorMapFloatOOBfill);

static void build_tmap(EncodeTiledFn enc, CUtensorMap* out, void* ptr,
                       uint64_t dim0, uint64_t dim1) {
    cuuint64_t dims[2] = {dim0, dim1};
    cuuint64_t strides[1] = {dim0};  // int8: bytes == elements
    cuuint32_t box[2] = {BKB, 128};
    cuuint32_t estr[2] = {1, 1};
    enc(out, CU_TENSOR_MAP_DATA_TYPE_UINT8, 2, ptr, dims, strides, box, estr,
        CU_TENSOR_MAP_INTERLEAVE_NONE, CU_TENSOR_MAP_SWIZZLE_128B,
        CU_TENSOR_MAP_L2_PROMOTION_L2_128B, CU_TENSOR_MAP_FLOAT_OOB_FILL_NONE);
}

extern "C" void kernel_launch(void* const* d_in, const int* in_sizes, int n_in,
                              void* d_out, int out_size) {
    const float* x      = (const float*)d_in[0];
    const int*   weight = (const int*)  d_in[1];
    const float* bias   = (const float*)d_in[2];
    const float* in_sc  = (const float*)d_in[3];
    const float* w_sc   = (const float*)d_in[4];
    float*       out    = (float*)d_out;

    int8_t* xq; cudaGetSymbolAddress((void**)&xq, g_xq);
    int8_t* wq; cudaGetSymbolAddress((void**)&wq, g_wq);

    // 1) quantize activations
    {
        int n4 = (MM * KK) / 4;          // 8388608, divisible by 1024
        int threads = 256;
        int blocks = n4 / (threads * 4);
        quantize_x_kernel<<<blocks, threads>>>(x, in_sc, xq);
    }
    // 2) repack + transpose weight
    {
        dim3 grid(NN / 32, KK / 128);
        repack_w_kernel<<<grid, 256>>>(weight);
    }
    // 3) tensor-core GEMM (mma.sync path — compiles on plain sm_103 target)
    {
        EncodeTiledFn enc = nullptr;
        cudaDriverEntryPointQueryResult qr;
        cudaGetDriverEntryPointByVersion("cuTensorMapEncodeTiled", (void**)&enc,
                                         12030, cudaEnableDefault, &qr);
        CUtensorMap tma_a, tma_b;
        build_tmap(enc, &tma_a, xq, KK, MM);
        build_tmap(enc, &tma_b, wq, KK, NN);

        cudaFuncSetAttribute(gemm_i8_mma_kernel,
                             cudaFuncAttributeMaxDynamicSharedMemorySize, SMEM_TOTAL);
        dim3 grid(NN / BN, MM / BM);
        gemm_i8_mma_kernel<<<grid, 256, SMEM_TOTAL>>>(tma_a, tma_b, bias,
                                                      in_sc, w_sc, out);
    }
}